// round 4
// baseline (speedup 1.0000x reference)
#include <cuda_runtime.h>
#include <math.h>

#define NB 32
#define NC 256
#define NH 64
#define NW 64
#define HW (NH*NW)          // 4096
#define HW4 (HW/4)          // 1024 float4 groups per (b,c) plane
#define KS 7
#define PAD 3

#define CHUNK 16            // images per chunk (16 * 4 MiB = 64 MiB, fits L2)
#define NCHUNK (NB / CHUNK)

__device__ float g_stats[NB * 2 * HW];   // per image: [max plane][mean plane]
__device__ float g_scale[NB * HW];       // sigmoid(conv)

// ---------------------------------------------------------------------------
// Kernel A: channel max+mean for images [b0, b0+CHUNK).
// Block = 512 threads = 32 pixel-groups (float4) x 16 channel-splits.
// ---------------------------------------------------------------------------
__global__ void __launch_bounds__(512) reduce_kernel(const float* __restrict__ x, int b0)
{
    __shared__ float4 s_max[16][32];
    __shared__ float4 s_sum[16][32];

    int tid = threadIdx.x;
    int pix = tid & 31;           // pixel-group lane (warp-contiguous)
    int cs  = tid >> 5;           // channel split 0..15

    int gp = blockIdx.x * 32 + pix;   // chunk-local float4 group
    int b  = b0 + (gp >> 10);
    int g  = gp & 1023;

    const float4* xb = reinterpret_cast<const float4*>(x)
                     + (size_t)b * NC * HW4 + (size_t)(cs * 16) * HW4 + g;

    float4 mx = make_float4(-INFINITY, -INFINITY, -INFINITY, -INFINITY);
    float4 sm = make_float4(0.f, 0.f, 0.f, 0.f);

    #pragma unroll
    for (int c = 0; c < 16; c++) {
        float4 v = __ldg(xb + c * HW4);
        mx.x = fmaxf(mx.x, v.x);  sm.x += v.x;
        mx.y = fmaxf(mx.y, v.y);  sm.y += v.y;
        mx.z = fmaxf(mx.z, v.z);  sm.z += v.z;
        mx.w = fmaxf(mx.w, v.w);  sm.w += v.w;
    }

    s_max[cs][pix] = mx;
    s_sum[cs][pix] = sm;
    __syncthreads();

    if (cs == 0) {
        #pragma unroll
        for (int k = 1; k < 16; k++) {
            float4 m = s_max[k][pix];
            float4 s = s_sum[k][pix];
            mx.x = fmaxf(mx.x, m.x);  sm.x += s.x;
            mx.y = fmaxf(mx.y, m.y);  sm.y += s.y;
            mx.z = fmaxf(mx.z, m.z);  sm.z += s.z;
            mx.w = fmaxf(mx.w, m.w);  sm.w += s.w;
        }
        const float inv = 1.0f / (float)NC;
        float4 mean4 = make_float4(sm.x * inv, sm.y * inv, sm.z * inv, sm.w * inv);

        float4* smax  = reinterpret_cast<float4*>(g_stats + (size_t)b * 2 * HW);
        float4* smean = smax + HW4;
        smax[g]  = mx;
        smean[g] = mean4;
    }
}

// ---------------------------------------------------------------------------
// Kernel B: 7x7 conv over [max, mean] stats -> sigmoid -> g_scale, per chunk.
// ---------------------------------------------------------------------------
__global__ void __launch_bounds__(128) conv_kernel(const float* __restrict__ wgt, int b0)
{
    __shared__ float sw[2 * KS * KS];
    if (threadIdx.x < 2 * KS * KS) sw[threadIdx.x] = wgt[threadIdx.x];
    __syncthreads();

    int idx = blockIdx.x * blockDim.x + threadIdx.x;   // chunk-local
    int b = b0 + (idx >> 10);
    int g = idx & 1023;
    int h  = g >> 4;
    int w0 = (g & 15) << 2;

    const float* smax  = g_stats + (size_t)b * 2 * HW;
    const float* smean = smax + HW;

    float acc0 = 0.f, acc1 = 0.f, acc2 = 0.f, acc3 = 0.f;

    #pragma unroll
    for (int kh = 0; kh < KS; kh++) {
        int ih = h + kh - PAD;
        if (ih < 0 || ih >= NH) continue;
        const float* rmax  = smax  + ih * NW;
        const float* rmean = smean + ih * NW;
        #pragma unroll
        for (int kw = 0; kw < KS; kw++) {
            float wm = sw[kh * KS + kw];
            float wa = sw[KS * KS + kh * KS + kw];
            int iw = w0 + kw - PAD;
            if (iw >= 0 && iw < NW)         { acc0 += __ldg(rmax + iw)     * wm + __ldg(rmean + iw)     * wa; }
            if (iw + 1 >= 0 && iw + 1 < NW) { acc1 += __ldg(rmax + iw + 1) * wm + __ldg(rmean + iw + 1) * wa; }
            if (iw + 2 >= 0 && iw + 2 < NW) { acc2 += __ldg(rmax + iw + 2) * wm + __ldg(rmean + iw + 2) * wa; }
            if (iw + 3 >= 0 && iw + 3 < NW) { acc3 += __ldg(rmax + iw + 3) * wm + __ldg(rmean + iw + 3) * wa; }
        }
    }

    float4 s;
    s.x = 1.0f / (1.0f + __expf(-acc0));
    s.y = 1.0f / (1.0f + __expf(-acc1));
    s.z = 1.0f / (1.0f + __expf(-acc2));
    s.w = 1.0f / (1.0f + __expf(-acc3));

    reinterpret_cast<float4*>(g_scale)[(size_t)b * HW4 + g] = s;
}

// ---------------------------------------------------------------------------
// Kernel C: out = x * scale for images [b0, b0+CHUNK). x-loads hit L2 (just
// read by reduce of the same chunk). .cs on both sides: evict x after use,
// stream out past L2.   idx bits (chunk-local): [b:4][cs:5][g:10]
// ---------------------------------------------------------------------------
#define CPT 8
__global__ void __launch_bounds__(256) scale_kernel(const float* __restrict__ x,
                                                    float* __restrict__ out, int b0)
{
    int idx = blockIdx.x * blockDim.x + threadIdx.x;
    int g  = idx & 1023;
    int cs = (idx >> 10) & 31;
    int b  = b0 + (idx >> 15);

    float4 s = __ldg(reinterpret_cast<const float4*>(g_scale) + (size_t)b * HW4 + g);

    const float4* xb = reinterpret_cast<const float4*>(x)
                     + ((size_t)b * NC + cs * CPT) * HW4 + g;
    float4* ob = reinterpret_cast<float4*>(out)
                     + ((size_t)b * NC + cs * CPT) * HW4 + g;

    #pragma unroll
    for (int c = 0; c < CPT; c++) {
        float4 v = __ldcs(xb + c * HW4);   // last use: evict-first
        v.x *= s.x; v.y *= s.y; v.z *= s.z; v.w *= s.w;
        __stcs(ob + c * HW4, v);           // streaming store
    }
}

extern "C" void kernel_launch(void* const* d_in, const int* in_sizes, int n_in,
                              void* d_out, int out_size)
{
    const float* x = (const float*)d_in[0];
    const float* w = (const float*)d_in[1];
    float* out = (float*)d_out;

    for (int ck = 0; ck < NCHUNK; ck++) {
        int b0 = ck * CHUNK;
        reduce_kernel<<<CHUNK * 32, 512>>>(x, b0);          // 512 blocks
        conv_kernel<<<CHUNK * 8, 128>>>(w, b0);             // 128 blocks
        scale_kernel<<<CHUNK * 32 * HW4 / 256, 256>>>(x, out, b0); // 2048 blocks
    }
}